// round 1
// baseline (speedup 1.0000x reference)
#include <cuda_runtime.h>
#include <stdint.h>

#define NBLK 1184   // 8 blocks per SM on 148 SMs
#define NTHR 256
#define NCOL 16

// Per-block partial sums/counts — fully overwritten every launch (graph-safe).
__device__ float g_psum[NBLK][NCOL];
__device__ float g_pcnt[NBLK][NCOL];
__device__ __align__(16) float g_mean[NCOL];

__device__ __forceinline__ bool is_nan_bits(float v) {
    return (__float_as_uint(v) & 0x7fffffffu) > 0x7f800000u;
}

__global__ void __launch_bounds__(NTHR) reduce_k(const float4* __restrict__ in, int n4) {
    int tid    = blockIdx.x * NTHR + threadIdx.x;
    int stride = gridDim.x * NTHR;          // multiple of 4 -> cg constant per thread
    float sx = 0.f, sy = 0.f, sz = 0.f, sw = 0.f;
    float cx = 0.f, cy = 0.f, cz = 0.f, cw = 0.f;
    for (int i = tid; i < n4; i += stride) {
        float4 v = in[i];
        if (!is_nan_bits(v.x)) { sx += v.x; cx += 1.f; }
        if (!is_nan_bits(v.y)) { sy += v.y; cy += 1.f; }
        if (!is_nan_bits(v.z)) { sz += v.z; cz += 1.f; }
        if (!is_nan_bits(v.w)) { sw += v.w; cw += 1.f; }
    }
    // Butterfly over distances 4,8,16: combines lanes with the same (lane % 4).
    #pragma unroll
    for (int d = 4; d < 32; d <<= 1) {
        sx += __shfl_xor_sync(0xffffffffu, sx, d);
        sy += __shfl_xor_sync(0xffffffffu, sy, d);
        sz += __shfl_xor_sync(0xffffffffu, sz, d);
        sw += __shfl_xor_sync(0xffffffffu, sw, d);
        cx += __shfl_xor_sync(0xffffffffu, cx, d);
        cy += __shfl_xor_sync(0xffffffffu, cy, d);
        cz += __shfl_xor_sync(0xffffffffu, cz, d);
        cw += __shfl_xor_sync(0xffffffffu, cw, d);
    }
    __shared__ float sh[2 * NCOL];
    if (threadIdx.x < 2 * NCOL) sh[threadIdx.x] = 0.f;
    __syncthreads();
    int lane = threadIdx.x & 31;
    if (lane < 4) {                         // lanes 0..3 hold column-group lane
        int c0 = lane * 4;                  // columns c0..c0+3 = (x,y,z,w)
        atomicAdd(&sh[c0 + 0], sx);
        atomicAdd(&sh[c0 + 1], sy);
        atomicAdd(&sh[c0 + 2], sz);
        atomicAdd(&sh[c0 + 3], sw);
        atomicAdd(&sh[NCOL + c0 + 0], cx);
        atomicAdd(&sh[NCOL + c0 + 1], cy);
        atomicAdd(&sh[NCOL + c0 + 2], cz);
        atomicAdd(&sh[NCOL + c0 + 3], cw);
    }
    __syncthreads();
    if (threadIdx.x < NCOL) {
        g_psum[blockIdx.x][threadIdx.x] = sh[threadIdx.x];
        g_pcnt[blockIdx.x][threadIdx.x] = sh[NCOL + threadIdx.x];
    }
}

__global__ void finalize_k() {
    __shared__ float fs[NCOL], fc[NCOL];
    int t = threadIdx.x;
    if (t < NCOL) { fs[t] = 0.f; fc[t] = 0.f; }
    __syncthreads();
    int col = t & (NCOL - 1);
    int grp = t >> 4;                        // 16 groups of 16 threads
    float s = 0.f, c = 0.f;
    for (int b = grp; b < NBLK; b += 16) {
        s += g_psum[b][col];
        c += g_pcnt[b][col];
    }
    atomicAdd(&fs[col], s);
    atomicAdd(&fc[col], c);
    __syncthreads();
    if (t < NCOL) g_mean[t] = fs[t] / fmaxf(fc[t], 1.0f);
}

__global__ void __launch_bounds__(NTHR) fill_k(const float4* __restrict__ in,
                                               float4* __restrict__ out, int n4) {
    int tid    = blockIdx.x * NTHR + threadIdx.x;
    int stride = gridDim.x * NTHR;
    // Each thread's float4 index mod 4 is constant -> one 4-column group.
    float4 m = reinterpret_cast<const float4*>(g_mean)[tid & 3];
    for (int i = tid; i < n4; i += stride) {
        float4 v = in[i];
        if (is_nan_bits(v.x)) v.x = m.x;
        if (is_nan_bits(v.y)) v.y = m.y;
        if (is_nan_bits(v.z)) v.z = m.z;
        if (is_nan_bits(v.w)) v.w = m.w;
        __stcs(&out[i], v);                  // streaming store: don't pollute L2
    }
}

extern "C" void kernel_launch(void* const* d_in, const int* in_sizes, int n_in,
                              void* d_out, int out_size) {
    const float4* in4 = (const float4*)d_in[0];
    float4* out4 = (float4*)d_out;
    int n4 = in_sizes[0] / 4;                // n is B*T*C, C=16 -> divisible by 4

    reduce_k<<<NBLK, NTHR>>>(in4, n4);
    finalize_k<<<1, NTHR>>>();
    fill_k<<<NBLK, NTHR>>>(in4, out4, n4);
}

// round 2
// speedup vs baseline: 1.1648x; 1.1648x over previous
#include <cuda_runtime.h>
#include <stdint.h>

#define NBLK 1184   // 8 blocks per SM on 148 SMs
#define NTHR 256
#define NCOL 16

// Per-block partial sums/counts — fully overwritten every launch (graph-safe).
__device__ float g_psum[NBLK][NCOL];
__device__ float g_pcnt[NBLK][NCOL];
__device__ __align__(16) float g_mean[NCOL];

__device__ __forceinline__ bool is_nan_bits(float v) {
    return (__float_as_uint(v) & 0x7fffffffu) > 0x7f800000u;
}

__device__ __forceinline__ void acc4(float4 v,
                                     float& sx, float& sy, float& sz, float& sw,
                                     float& cx, float& cy, float& cz, float& cw) {
    if (!is_nan_bits(v.x)) { sx += v.x; cx += 1.f; }
    if (!is_nan_bits(v.y)) { sy += v.y; cy += 1.f; }
    if (!is_nan_bits(v.z)) { sz += v.z; cz += 1.f; }
    if (!is_nan_bits(v.w)) { sw += v.w; cw += 1.f; }
}

__global__ void __launch_bounds__(NTHR) reduce_k(const float4* __restrict__ in, int n4) {
    int tid    = blockIdx.x * NTHR + threadIdx.x;
    int stride = gridDim.x * NTHR;          // multiple of 4 -> column group constant per thread
    float sx = 0.f, sy = 0.f, sz = 0.f, sw = 0.f;
    float cx = 0.f, cy = 0.f, cz = 0.f, cw = 0.f;

    int i = tid;
    // Unrolled x4: 4 independent LDG.128 in flight per iteration (MLP_p1 = 4).
    for (; i + 3 * stride < n4; i += 4 * stride) {
        float4 v0 = in[i];
        float4 v1 = in[i + stride];
        float4 v2 = in[i + 2 * stride];
        float4 v3 = in[i + 3 * stride];
        acc4(v0, sx, sy, sz, sw, cx, cy, cz, cw);
        acc4(v1, sx, sy, sz, sw, cx, cy, cz, cw);
        acc4(v2, sx, sy, sz, sw, cx, cy, cz, cw);
        acc4(v3, sx, sy, sz, sw, cx, cy, cz, cw);
    }
    for (; i < n4; i += stride) {
        acc4(in[i], sx, sy, sz, sw, cx, cy, cz, cw);
    }

    // Butterfly over distances 4,8,16: combines lanes with the same (lane % 4).
    #pragma unroll
    for (int d = 4; d < 32; d <<= 1) {
        sx += __shfl_xor_sync(0xffffffffu, sx, d);
        sy += __shfl_xor_sync(0xffffffffu, sy, d);
        sz += __shfl_xor_sync(0xffffffffu, sz, d);
        sw += __shfl_xor_sync(0xffffffffu, sw, d);
        cx += __shfl_xor_sync(0xffffffffu, cx, d);
        cy += __shfl_xor_sync(0xffffffffu, cy, d);
        cz += __shfl_xor_sync(0xffffffffu, cz, d);
        cw += __shfl_xor_sync(0xffffffffu, cw, d);
    }
    __shared__ float sh[2 * NCOL];
    if (threadIdx.x < 2 * NCOL) sh[threadIdx.x] = 0.f;
    __syncthreads();
    int lane = threadIdx.x & 31;
    if (lane < 4) {                         // lanes 0..3 hold distinct column groups
        int c0 = lane * 4;
        atomicAdd(&sh[c0 + 0], sx);
        atomicAdd(&sh[c0 + 1], sy);
        atomicAdd(&sh[c0 + 2], sz);
        atomicAdd(&sh[c0 + 3], sw);
        atomicAdd(&sh[NCOL + c0 + 0], cx);
        atomicAdd(&sh[NCOL + c0 + 1], cy);
        atomicAdd(&sh[NCOL + c0 + 2], cz);
        atomicAdd(&sh[NCOL + c0 + 3], cw);
    }
    __syncthreads();
    if (threadIdx.x < NCOL) {
        g_psum[blockIdx.x][threadIdx.x] = sh[threadIdx.x];
        g_pcnt[blockIdx.x][threadIdx.x] = sh[NCOL + threadIdx.x];
    }
}

__global__ void finalize_k() {
    __shared__ float fs[NCOL], fc[NCOL];
    int t = threadIdx.x;
    if (t < NCOL) { fs[t] = 0.f; fc[t] = 0.f; }
    __syncthreads();
    int col = t & (NCOL - 1);
    int grp = t >> 4;                        // 16 groups of 16 threads
    float s = 0.f, c = 0.f;
    for (int b = grp; b < NBLK; b += 16) {
        s += g_psum[b][col];
        c += g_pcnt[b][col];
    }
    atomicAdd(&fs[col], s);
    atomicAdd(&fc[col], c);
    __syncthreads();
    if (t < NCOL) g_mean[t] = fs[t] / fmaxf(fc[t], 1.0f);
}

// REVERSED traversal: the tail of the input is the most recently L2-resident
// after reduce_k's forward stream, so reading back-to-front harvests L2 hits
// instead of LRU-thrashing. Streaming stores (evict-first) protect input lines.
__global__ void __launch_bounds__(NTHR) fill_k(const float4* __restrict__ in,
                                               float4* __restrict__ out, int n4) {
    int lin    = blockIdx.x * NTHR + threadIdx.x;
    int stride = gridDim.x * NTHR;           // multiple of 4
    int i0     = n4 - 1 - lin;
    if (i0 < 0) return;
    // (i mod 4) is constant along the descending stride -> one column group.
    float4 m = reinterpret_cast<const float4*>(g_mean)[i0 & 3];

    int i = i0;
    for (; i - 3 * stride >= 0; i -= 4 * stride) {
        float4 v0 = __ldcg(&in[i]);
        float4 v1 = __ldcg(&in[i - stride]);
        float4 v2 = __ldcg(&in[i - 2 * stride]);
        float4 v3 = __ldcg(&in[i - 3 * stride]);
        if (is_nan_bits(v0.x)) v0.x = m.x;
        if (is_nan_bits(v0.y)) v0.y = m.y;
        if (is_nan_bits(v0.z)) v0.z = m.z;
        if (is_nan_bits(v0.w)) v0.w = m.w;
        if (is_nan_bits(v1.x)) v1.x = m.x;
        if (is_nan_bits(v1.y)) v1.y = m.y;
        if (is_nan_bits(v1.z)) v1.z = m.z;
        if (is_nan_bits(v1.w)) v1.w = m.w;
        if (is_nan_bits(v2.x)) v2.x = m.x;
        if (is_nan_bits(v2.y)) v2.y = m.y;
        if (is_nan_bits(v2.z)) v2.z = m.z;
        if (is_nan_bits(v2.w)) v2.w = m.w;
        if (is_nan_bits(v3.x)) v3.x = m.x;
        if (is_nan_bits(v3.y)) v3.y = m.y;
        if (is_nan_bits(v3.z)) v3.z = m.z;
        if (is_nan_bits(v3.w)) v3.w = m.w;
        __stcs(&out[i], v0);
        __stcs(&out[i - stride], v1);
        __stcs(&out[i - 2 * stride], v2);
        __stcs(&out[i - 3 * stride], v3);
    }
    for (; i >= 0; i -= stride) {
        float4 v = __ldcg(&in[i]);
        if (is_nan_bits(v.x)) v.x = m.x;
        if (is_nan_bits(v.y)) v.y = m.y;
        if (is_nan_bits(v.z)) v.z = m.z;
        if (is_nan_bits(v.w)) v.w = m.w;
        __stcs(&out[i], v);
    }
}

extern "C" void kernel_launch(void* const* d_in, const int* in_sizes, int n_in,
                              void* d_out, int out_size) {
    const float4* in4 = (const float4*)d_in[0];
    float4* out4 = (float4*)d_out;
    int n4 = in_sizes[0] / 4;                // B*T*C with C=16 -> divisible by 4

    reduce_k<<<NBLK, NTHR>>>(in4, n4);
    finalize_k<<<1, NTHR>>>();
    fill_k<<<NBLK, NTHR>>>(in4, out4, n4);
}